// round 1
// baseline (speedup 1.0000x reference)
#include <cuda_runtime.h>

#define SQ 2048
#define DM 1024
#define NB 2
#define NH 16
#define DK 64

// Scratch (allocation-free: __device__ globals)
__device__ float g_q[(long)NB*SQ*DM];
__device__ float g_k[(long)NB*SQ*DM];
__device__ float g_v[(long)NB*SQ*DM];
__device__ float g_ctx[(long)NB*SQ*DM];

__device__ __forceinline__ const float* selc(const float* p, int s) {
    switch (s) {
        case 0: return g_q;
        case 1: return g_k;
        case 2: return g_v;
        case 3: return g_ctx;
        default: return p;
    }
}
__device__ __forceinline__ float* selm(float* p, int s) {
    switch (s) {
        case 0: return g_q;
        case 1: return g_k;
        case 2: return g_v;
        case 3: return g_ctx;
        default: return p;
    }
}

// C[m,n] = alpha * sum_k A[m,k]*B[n,k]  (+ bias[n])
// Batched via blockIdx.z: b = z/H, h = z%H; bases offset by (b,h) strides.
// Tiles: 128x128, BK=16, 256 threads, 8x8 per thread.
__global__ __launch_bounds__(256) void sgemm_nt(
    const float* __restrict__ Ain, int asel, int lda, long sAb, long sAh,
    const float* __restrict__ Bin, int bsel, int ldb, long sBb, long sBh,
    float* __restrict__ Cout, int csel, int ldc, long sCz,
    int K, float alpha, const float* __restrict__ bias, int H)
{
    const float* A = selc(Ain, asel);
    const float* Bp = selc(Bin, bsel);
    float* C = selm(Cout, csel);

    int z = blockIdx.z;
    int b = z / H, h = z % H;
    A += (long)b * sAb + (long)h * sAh;
    Bp += (long)b * sBb + (long)h * sBh;
    C += (long)z * sCz;

    __shared__ float As[16][128];
    __shared__ float Bs[16][128];

    int tid = threadIdx.x;
    int tx = tid & 15;        // n sub-tile
    int ty = tid >> 4;        // m sub-tile
    long m0 = (long)blockIdx.y * 128;
    long n0 = (long)blockIdx.x * 128;

    int lr = tid >> 2;        // 0..63 loader row
    int lc = (tid & 3) * 4;   // 0,4,8,12 loader col

    float acc[8][8] = {};

    for (int k0 = 0; k0 < K; k0 += 16) {
#pragma unroll
        for (int r = 0; r < 2; r++) {
            int row = lr + r * 64;
            float4 av = *(const float4*)(A + (m0 + row) * (long)lda + k0 + lc);
            As[lc + 0][row] = av.x;
            As[lc + 1][row] = av.y;
            As[lc + 2][row] = av.z;
            As[lc + 3][row] = av.w;
            float4 bv = *(const float4*)(Bp + (n0 + row) * (long)ldb + k0 + lc);
            Bs[lc + 0][row] = bv.x;
            Bs[lc + 1][row] = bv.y;
            Bs[lc + 2][row] = bv.z;
            Bs[lc + 3][row] = bv.w;
        }
        __syncthreads();
#pragma unroll
        for (int kk = 0; kk < 16; kk++) {
            float ra[8], rb[8];
            *(float4*)&ra[0] = *(const float4*)&As[kk][ty * 8];
            *(float4*)&ra[4] = *(const float4*)&As[kk][ty * 8 + 4];
            *(float4*)&rb[0] = *(const float4*)&Bs[kk][tx * 8];
            *(float4*)&rb[4] = *(const float4*)&Bs[kk][tx * 8 + 4];
#pragma unroll
            for (int i = 0; i < 8; i++)
#pragma unroll
                for (int j = 0; j < 8; j++)
                    acc[i][j] += ra[i] * rb[j];
        }
        __syncthreads();
    }

#pragma unroll
    for (int i = 0; i < 8; i++) {
        long row = m0 + ty * 8 + i;
#pragma unroll
        for (int j0 = 0; j0 < 8; j0 += 4) {
            long col = n0 + tx * 8 + j0;
            float4 o;
            o.x = acc[i][j0 + 0] * alpha + (bias ? bias[col + 0] : 0.f);
            o.y = acc[i][j0 + 1] * alpha + (bias ? bias[col + 1] : 0.f);
            o.z = acc[i][j0 + 2] * alpha + (bias ? bias[col + 2] : 0.f);
            o.w = acc[i][j0 + 3] * alpha + (bias ? bias[col + 3] : 0.f);
            *(float4*)(C + row * (long)ldc + col) = o;
        }
    }
}

// In-place row softmax, one block per row of 2048 floats.
__global__ __launch_bounds__(256) void softmax_rows(float* __restrict__ scores) {
    float* p = scores + (long)blockIdx.x * SQ;
    int t = threadIdx.x;
    int lane = t & 31, wid = t >> 5;

    float4 a = *(const float4*)(p + t * 4);
    float4 c = *(const float4*)(p + 1024 + t * 4);

    float m = fmaxf(fmaxf(fmaxf(a.x, a.y), fmaxf(a.z, a.w)),
                    fmaxf(fmaxf(c.x, c.y), fmaxf(c.z, c.w)));
#pragma unroll
    for (int off = 16; off; off >>= 1)
        m = fmaxf(m, __shfl_xor_sync(0xffffffffu, m, off));

    __shared__ float red[8];
    if (lane == 0) red[wid] = m;
    __syncthreads();
    float rm = red[0];
#pragma unroll
    for (int i = 1; i < 8; i++) rm = fmaxf(rm, red[i]);
    __syncthreads();

    a.x = __expf(a.x - rm); a.y = __expf(a.y - rm);
    a.z = __expf(a.z - rm); a.w = __expf(a.w - rm);
    c.x = __expf(c.x - rm); c.y = __expf(c.y - rm);
    c.z = __expf(c.z - rm); c.w = __expf(c.w - rm);

    float s = a.x + a.y + a.z + a.w + c.x + c.y + c.z + c.w;
#pragma unroll
    for (int off = 16; off; off >>= 1)
        s += __shfl_xor_sync(0xffffffffu, s, off);
    if (lane == 0) red[wid] = s;
    __syncthreads();
    float rs = red[0];
#pragma unroll
    for (int i = 1; i < 8; i++) rs += red[i];

    float inv = 1.f / rs;
    a.x *= inv; a.y *= inv; a.z *= inv; a.w *= inv;
    c.x *= inv; c.y *= inv; c.z *= inv; c.w *= inv;

    *(float4*)(p + t * 4) = a;
    *(float4*)(p + 1024 + t * 4) = c;
}

// blended = P @ V : per (b,h), A = P [2048 x 2048] (ld 2048, row-major, NN),
// B = v slice [2048 x 64] (ld 1024), C -> g_ctx[b, s, h*64 + d] (ld 1024).
// Tiles: 128x64, BK=16, 256 threads, 8x4 per thread.
__global__ __launch_bounds__(256) void pv_nn(const float* __restrict__ scores) {
    int z = blockIdx.z;
    int b = z >> 4, h = z & 15;
    const float* Ap = scores + (long)z * SQ * SQ;
    const float* Bp = g_v + (long)b * SQ * DM + h * DK;
    float* Cp = g_ctx + (long)b * SQ * DM + h * DK;

    __shared__ float As[16][128];
    __shared__ float Bs[16][64];

    int tid = threadIdx.x;
    int tx = tid & 15;    // n sub-tile (cols tx*4)
    int ty = tid >> 4;    // m sub-tile (rows ty*8)
    long m0 = (long)blockIdx.y * 128;

    int ar = tid >> 2;         // 0..63
    int ac = (tid & 3) * 4;    // 0,4,8,12
    int br = tid >> 4;         // 0..15
    int bc = (tid & 15) * 4;   // 0..60

    float acc[8][4] = {};

    for (int k0 = 0; k0 < SQ; k0 += 16) {
#pragma unroll
        for (int r = 0; r < 2; r++) {
            int row = ar + r * 64;
            float4 av = *(const float4*)(Ap + (m0 + row) * (long)SQ + k0 + ac);
            As[ac + 0][row] = av.x;
            As[ac + 1][row] = av.y;
            As[ac + 2][row] = av.z;
            As[ac + 3][row] = av.w;
        }
        *(float4*)&Bs[br][bc] = *(const float4*)(Bp + (long)(k0 + br) * DM + bc);
        __syncthreads();
#pragma unroll
        for (int kk = 0; kk < 16; kk++) {
            float ra[8], rb[4];
            *(float4*)&ra[0] = *(const float4*)&As[kk][ty * 8];
            *(float4*)&ra[4] = *(const float4*)&As[kk][ty * 8 + 4];
            *(float4*)&rb[0] = *(const float4*)&Bs[kk][tx * 4];
#pragma unroll
            for (int i = 0; i < 8; i++)
#pragma unroll
                for (int j = 0; j < 4; j++)
                    acc[i][j] += ra[i] * rb[j];
        }
        __syncthreads();
    }

#pragma unroll
    for (int i = 0; i < 8; i++) {
        long row = m0 + ty * 8 + i;
        float4 o;
        o.x = acc[i][0]; o.y = acc[i][1]; o.z = acc[i][2]; o.w = acc[i][3];
        *(float4*)(Cp + row * (long)DM + tx * 4) = o;
    }
}

extern "C" void kernel_launch(void* const* d_in, const int* in_sizes, int n_in,
                              void* d_out, int out_size) {
    const float* query = (const float*)d_in[0];
    const float* key   = (const float*)d_in[1];
    const float* value = (const float*)d_in[2];
    const float* Wq = (const float*)d_in[3];
    const float* bq = (const float*)d_in[4];
    const float* Wk = (const float*)d_in[5];
    const float* bk = (const float*)d_in[6];
    const float* Wv = (const float*)d_in[7];
    const float* bv = (const float*)d_in[8];
    const float* Wo = (const float*)d_in[9];
    const float* bo = (const float*)d_in[10];

    float* out = (float*)d_out;
    float* scores = out + (long)NB * SQ * DM;   // [B, H, S, S] after the [B,S,D] out block

    dim3 gproj(8, 32, 1);    // N=1024/128, M=4096/128
    // q = query @ Wq^T + bq   -> g_q (csel 0)
    sgemm_nt<<<gproj, 256>>>(query, -1, DM, 0, 0, Wq, -1, DM, 0, 0,
                             nullptr, 0, DM, 0, DM, 1.f, bq, 1);
    // k -> g_k (csel 1)
    sgemm_nt<<<gproj, 256>>>(key, -1, DM, 0, 0, Wk, -1, DM, 0, 0,
                             nullptr, 1, DM, 0, DM, 1.f, bk, 1);
    // v -> g_v (csel 2)
    sgemm_nt<<<gproj, 256>>>(value, -1, DM, 0, 0, Wv, -1, DM, 0, 0,
                             nullptr, 2, DM, 0, DM, 1.f, bv, 1);

    // logits = (q @ k^T) / 8 per (b,h), written into score region of d_out
    dim3 gqk(16, 16, NB * NH);
    sgemm_nt<<<gqk, 256>>>(nullptr, 0, DM, (long)SQ * DM, DK,
                           nullptr, 1, DM, (long)SQ * DM, DK,
                           scores, -1, SQ, (long)SQ * SQ,
                           DK, 0.125f, nullptr, NH);

    // softmax rows in place
    softmax_rows<<<NB * NH * SQ, 256>>>(scores);

    // blended = P @ v -> g_ctx (concat-head layout)
    dim3 gpv(1, 16, NB * NH);
    pv_nn<<<gpv, 256>>>(scores);

    // out = ctx @ Wo^T + bo
    sgemm_nt<<<gproj, 256>>>(nullptr, 3, DM, 0, 0, Wo, -1, DM, 0, 0,
                             out, -1, DM, 0, DM, 1.f, bo, 1);
}

// round 3
// speedup vs baseline: 1.7116x; 1.7116x over previous
#include <cuda_runtime.h>
#include <cuda_bf16.h>
#include <cstdint>

#define SQ 2048
#define DM 1024
#define NB 2
#define NH 16
#define DK 64

// Scratch (allocation-free: __device__ globals)
__device__ float g_q[(long)NB*SQ*DM];
__device__ float g_k[(long)NB*SQ*DM];
__device__ float g_v[(long)NB*SQ*DM];
__device__ float g_ctx[(long)NB*SQ*DM];
__device__ float g_vt[(long)NB*DM*SQ];   // v transposed: [b, d, s]

__device__ __forceinline__ const float* selc(const float* p, int s) {
    switch (s) {
        case 0: return g_q;
        case 1: return g_k;
        case 2: return g_v;
        case 3: return g_ctx;
        case 4: return g_vt;
        default: return p;
    }
}
__device__ __forceinline__ float* selm(float* p, int s) {
    switch (s) {
        case 0: return g_q;
        case 1: return g_k;
        case 2: return g_v;
        case 3: return g_ctx;
        default: return p;
    }
}

__device__ __forceinline__ uint32_t smem_u32(const void* p) {
    uint32_t a;
    asm("{ .reg .u64 t; cvta.to.shared.u64 t, %1; cvt.u32.u64 %0, t; }" : "=r"(a) : "l"(p));
    return a;
}

#define LDSM4(r0, r1, r2, r3, addr) \
    asm volatile("ldmatrix.sync.aligned.m8n8.x4.shared.b16 {%0,%1,%2,%3}, [%4];" \
        : "=r"(r0), "=r"(r1), "=r"(r2), "=r"(r3) : "r"(addr))

#define MMA16816(d, a, b) \
    asm volatile("mma.sync.aligned.m16n8k16.row.col.f32.bf16.bf16.f32 " \
        "{%0,%1,%2,%3}, {%4,%5,%6,%7}, {%8,%9}, {%0,%1,%2,%3};" \
        : "+f"((d)[0]), "+f"((d)[1]), "+f"((d)[2]), "+f"((d)[3]) \
        : "r"((a)[0]), "r"((a)[1]), "r"((a)[2]), "r"((a)[3]), "r"((b)[0]), "r"((b)[1]))

// Convert float4 -> bf16 hi/lo, store into SW128-swizzled K-major tile (row = 64 bf16 = 128B)
__device__ __forceinline__ void cvt_store(char* smem, int offHi, int offLo, int row, int c4, float4 v) {
    uint32_t hi01, hi23;
    asm("cvt.rn.bf16x2.f32 %0, %1, %2;" : "=r"(hi01) : "f"(v.y), "f"(v.x));
    asm("cvt.rn.bf16x2.f32 %0, %1, %2;" : "=r"(hi23) : "f"(v.w), "f"(v.z));
    float f0 = __uint_as_float(hi01 << 16);
    float f1 = __uint_as_float(hi01 & 0xffff0000u);
    float f2 = __uint_as_float(hi23 << 16);
    float f3 = __uint_as_float(hi23 & 0xffff0000u);
    uint32_t lo01, lo23;
    asm("cvt.rn.bf16x2.f32 %0, %1, %2;" : "=r"(lo01) : "f"(v.y - f1), "f"(v.x - f0));
    asm("cvt.rn.bf16x2.f32 %0, %1, %2;" : "=r"(lo23) : "f"(v.w - f3), "f"(v.z - f2));
    uint32_t off = row * 128 + (c4 << 1);
    uint32_t sw = off ^ ((off >> 3) & 0x70);
    *(uint32_t*)(smem + offHi + sw)     = hi01;
    *(uint32_t*)(smem + offHi + sw + 4) = hi23;
    *(uint32_t*)(smem + offLo + sw)     = lo01;
    *(uint32_t*)(smem + offLo + sw + 4) = lo23;
}

// ---------------- HMMA GEMM (bf16x3 split, fp32 accumulate) ----------------
// C[m,n] = alpha * sum_k A[m,k]*B[n,k] (+ bias[n]).  A, B both K-contiguous (NT).
// Block: 128 x NTILE, K-chunks of 64. 256 threads = 8 warps, 4(M) x 2(N) warp grid.
template<int NTILE>
__global__ __launch_bounds__(256) void mm_mma(
    const float* __restrict__ Ain, int asel, int lda, long sAb, long sAh,
    const float* __restrict__ Bin, int bsel, int ldb, long sBb, long sBh,
    float* __restrict__ Cout, int csel, int ldc, long sCb, long sCh,
    int K, float alpha, const float* __restrict__ bias, int H)
{
    extern __shared__ char smem[];
    constexpr int ABYT = 128 * 64 * 2;
    constexpr int BBYT = NTILE * 64 * 2;
    constexpr int OFF_AHI = 0;
    constexpr int OFF_ALO = ABYT;
    constexpr int OFF_BHI = 2 * ABYT;
    constexpr int OFF_BLO = 2 * ABYT + BBYT;
    constexpr int WN = NTILE / 2;   // warp N extent (64 or 32)
    constexpr int NG = WN / 8;      // 8-wide n-groups per warp (8 or 4)

    uint32_t sb = smem_u32(smem);
    int tid = threadIdx.x, wid = tid >> 5, lane = tid & 31;
    int warp_m = wid & 3, warp_n = wid >> 2;

    const float* A = selc(Ain, asel);
    const float* B = selc(Bin, bsel);
    float* C = selm(Cout, csel);
    int z = blockIdx.z, b = z / H, h = z - b * H;
    A += (long)b * sAb + (long)h * sAh;
    B += (long)b * sBb + (long)h * sBh;
    C += (long)b * sCb + (long)h * sCh;
    long m0 = (long)blockIdx.y * 128;
    long n0 = (long)blockIdx.x * NTILE;

    // per-lane ldmatrix row/col components (within a 16-row, 32-byte k-step window)
    int lrow = lane & 15;            // row within 16-block
    int lcb = (lane >> 4) << 4;      // 0 or 16 bytes (8-element column group)

    float acc[2][NG][4];
#pragma unroll
    for (int im = 0; im < 2; im++)
#pragma unroll
        for (int g = 0; g < NG; g++)
#pragma unroll
            for (int j = 0; j < 4; j++) acc[im][g][j] = 0.f;

    const int nchunks = K >> 6;
    for (int c = 0; c < nchunks; c++) {
        int k0 = c << 6;
#pragma unroll
        for (int i = 0; i < 8; i++) {           // A: 128x64 = 2048 float4
            int idx4 = i * 256 + tid;
            int row = idx4 >> 4;
            int c4 = (idx4 & 15) << 2;
            float4 v = *(const float4*)(A + (m0 + row) * (long)lda + k0 + c4);
            cvt_store(smem, OFF_AHI, OFF_ALO, row, c4, v);
        }
#pragma unroll
        for (int i = 0; i < NTILE / 16; i++) {  // B: NTILEx64
            int idx4 = i * 256 + tid;
            int row = idx4 >> 4;
            int c4 = (idx4 & 15) << 2;
            float4 v = *(const float4*)(B + (n0 + row) * (long)ldb + k0 + c4);
            cvt_store(smem, OFF_BHI, OFF_BLO, row, c4, v);
        }
        __syncthreads();

#pragma unroll
        for (int pass = 0; pass < 3; pass++) {
            int aoff = (pass == 2) ? OFF_ALO : OFF_AHI;
            int boff = (pass == 1) ? OFF_BLO : OFF_BHI;
#pragma unroll
            for (int ks = 0; ks < 4; ks++) {
                int cb = ks * 32 + lcb;
                uint32_t afr[2][4];
#pragma unroll
                for (int im = 0; im < 2; im++) {
                    int row = warp_m * 32 + im * 16 + lrow;
                    uint32_t addr = sb + aoff + row * 128 + (cb ^ ((row & 7) << 4));
                    LDSM4(afr[im][0], afr[im][1], afr[im][2], afr[im][3], addr);
                }
                uint32_t bfr[NG][2];
#pragma unroll
                for (int g2 = 0; g2 < NG / 2; g2++) {
                    int row = warp_n * WN + g2 * 16 + lrow;
                    uint32_t addr = sb + boff + row * 128 + (cb ^ ((row & 7) << 4));
                    uint32_t m0r, m1r, m2r, m3r;
                    LDSM4(m0r, m1r, m2r, m3r, addr);
                    bfr[2 * g2][0] = m0r; bfr[2 * g2][1] = m2r;
                    bfr[2 * g2 + 1][0] = m1r; bfr[2 * g2 + 1][1] = m3r;
                }
#pragma unroll
                for (int im = 0; im < 2; im++)
#pragma unroll
                    for (int g = 0; g < NG; g++)
                        MMA16816(acc[im][g], afr[im], bfr[g]);
            }
        }
        __syncthreads();
    }

    // Epilogue: thread owns rows {r, r+8} x col pairs per n-group
#pragma unroll
    for (int im = 0; im < 2; im++) {
        long r0 = m0 + warp_m * 32 + im * 16 + (lane >> 2);
#pragma unroll
        for (int g = 0; g < NG; g++) {
            long col = n0 + warp_n * WN + g * 8 + (lane & 3) * 2;
            float bx = bias ? bias[col] : 0.f;
            float by = bias ? bias[col + 1] : 0.f;
            float2 o0, o1;
            o0.x = acc[im][g][0] * alpha + bx;
            o0.y = acc[im][g][1] * alpha + by;
            o1.x = acc[im][g][2] * alpha + bx;
            o1.y = acc[im][g][3] * alpha + by;
            *(float2*)(C + r0 * (long)ldc + col) = o0;
            *(float2*)(C + (r0 + 8) * (long)ldc + col) = o1;
        }
    }
}

// v [b, s, d] -> vt [b, d, s]
__global__ __launch_bounds__(256) void transpose_v() {
    __shared__ float t[32][33];
    int b = blockIdx.z;
    int d0 = blockIdx.x * 32, k0 = blockIdx.y * 32;
    const float* src = g_v + (long)b * SQ * DM;
    float* dst = g_vt + (long)b * DM * SQ;
    int tx = threadIdx.x, ty = threadIdx.y;
#pragma unroll
    for (int i = 0; i < 32; i += 8)
        t[ty + i][tx] = src[(long)(k0 + ty + i) * DM + d0 + tx];
    __syncthreads();
#pragma unroll
    for (int i = 0; i < 32; i += 8)
        dst[(long)(d0 + ty + i) * SQ + k0 + tx] = t[tx][ty + i];
}

// In-place row softmax, one block per row of 2048 floats.
__global__ __launch_bounds__(256) void softmax_rows(float* __restrict__ scores) {
    float* p = scores + (long)blockIdx.x * SQ;
    int t = threadIdx.x;
    int lane = t & 31, wid = t >> 5;

    float4 a = *(const float4*)(p + t * 4);
    float4 c = *(const float4*)(p + 1024 + t * 4);

    float m = fmaxf(fmaxf(fmaxf(a.x, a.y), fmaxf(a.z, a.w)),
                    fmaxf(fmaxf(c.x, c.y), fmaxf(c.z, c.w)));
#pragma unroll
    for (int off = 16; off; off >>= 1)
        m = fmaxf(m, __shfl_xor_sync(0xffffffffu, m, off));

    __shared__ float red[8];
    if (lane == 0) red[wid] = m;
    __syncthreads();
    float rm = red[0];
#pragma unroll
    for (int i = 1; i < 8; i++) rm = fmaxf(rm, red[i]);
    __syncthreads();

    a.x = __expf(a.x - rm); a.y = __expf(a.y - rm);
    a.z = __expf(a.z - rm); a.w = __expf(a.w - rm);
    c.x = __expf(c.x - rm); c.y = __expf(c.y - rm);
    c.z = __expf(c.z - rm); c.w = __expf(c.w - rm);

    float s = a.x + a.y + a.z + a.w + c.x + c.y + c.z + c.w;
#pragma unroll
    for (int off = 16; off; off >>= 1)
        s += __shfl_xor_sync(0xffffffffu, s, off);
    if (lane == 0) red[wid] = s;
    __syncthreads();
    float rs = red[0];
#pragma unroll
    for (int i = 1; i < 8; i++) rs += red[i];

    float inv = 1.f / rs;
    a.x *= inv; a.y *= inv; a.z *= inv; a.w *= inv;
    c.x *= inv; c.y *= inv; c.z *= inv; c.w *= inv;

    *(float4*)(p + t * 4) = a;
    *(float4*)(p + 1024 + t * 4) = c;
}

extern "C" void kernel_launch(void* const* d_in, const int* in_sizes, int n_in,
                              void* d_out, int out_size) {
    const float* query = (const float*)d_in[0];
    const float* key   = (const float*)d_in[1];
    const float* value = (const float*)d_in[2];
    const float* Wq = (const float*)d_in[3];
    const float* bq = (const float*)d_in[4];
    const float* Wk = (const float*)d_in[5];
    const float* bk = (const float*)d_in[6];
    const float* Wv = (const float*)d_in[7];
    const float* bv = (const float*)d_in[8];
    const float* Wo = (const float*)d_in[9];
    const float* bo = (const float*)d_in[10];

    float* out = (float*)d_out;
    float* scores = out + (long)NB * SQ * DM;   // [B, H, S, S]

    const int SMEM128 = 4 * (128 * 64 * 2);                       // 65536
    const int SMEM64  = 2 * (128 * 64 * 2) + 2 * (64 * 64 * 2);   // 49152
    cudaFuncSetAttribute(mm_mma<128>, cudaFuncAttributeMaxDynamicSharedMemorySize, SMEM128);
    cudaFuncSetAttribute(mm_mma<64>,  cudaFuncAttributeMaxDynamicSharedMemorySize, SMEM64);

    dim3 gproj(8, 32, 1);
    // q/k/v projections -> g_q/g_k/g_v
    mm_mma<128><<<gproj, 256, SMEM128>>>(query, -1, DM, 0, 0, Wq, -1, DM, 0, 0,
                                         nullptr, 0, DM, 0, 0, DM, 1.f, bq, 1);
    mm_mma<128><<<gproj, 256, SMEM128>>>(key, -1, DM, 0, 0, Wk, -1, DM, 0, 0,
                                         nullptr, 1, DM, 0, 0, DM, 1.f, bk, 1);
    mm_mma<128><<<gproj, 256, SMEM128>>>(value, -1, DM, 0, 0, Wv, -1, DM, 0, 0,
                                         nullptr, 2, DM, 0, 0, DM, 1.f, bv, 1);

    // logits = (q @ k^T) / 8 into score region
    dim3 gqk(16, 16, NB * NH);
    mm_mma<128><<<gqk, 256, SMEM128>>>(nullptr, 0, DM, (long)SQ * DM, DK,
                                       nullptr, 1, DM, (long)SQ * DM, DK,
                                       scores, -1, SQ, (long)NH * SQ * SQ, (long)SQ * SQ,
                                       DK, 0.125f, nullptr, NH);

    // v -> vt (K-major for PV)
    transpose_v<<<dim3(32, 64, NB), dim3(32, 8)>>>();

    // softmax rows in place
    softmax_rows<<<NB * NH * SQ, 256>>>(scores);

    // blended = P @ v -> g_ctx
    dim3 gpv(1, 16, NB * NH);
    mm_mma<64><<<gpv, 256, SMEM64>>>(scores, -1, SQ, (long)NH * SQ * SQ, (long)SQ * SQ,
                                     nullptr, 4, SQ, (long)DM * SQ, (long)DK * SQ,
                                     nullptr, 3, DM, (long)SQ * DM, DK,
                                     SQ, 1.f, nullptr, NH);

    // out = ctx @ Wo^T + bo
    mm_mma<128><<<gproj, 256, SMEM128>>>(nullptr, 3, DM, 0, 0, Wo, -1, DM, 0, 0,
                                         out, -1, DM, 0, 0, DM, 1.f, bo, 1);
}

// round 4
// speedup vs baseline: 1.7144x; 1.0017x over previous
#include <cuda_runtime.h>
#include <cuda_bf16.h>
#include <cstdint>

#define SQ 2048
#define DM 1024
#define NB 2
#define NH 16
#define DK 64
#define MI (1024L * 1024L)

// One big bf16 scratch buffer (allocation-free __device__ global), 144MB
__device__ __align__(256) __nv_bfloat16 g_buf[72 * MI];

// element offsets into g_buf
#define O_INH (0 * MI)        // query/key/value hi: 3 x 4M
#define O_INL (12 * MI)
#define O_WH  (24 * MI)       // Wq,Wk,Wv,Wo hi: 4 x 1M
#define O_WL  (28 * MI)
#define O_QH  (32 * MI)
#define O_QL  (36 * MI)
#define O_KH  (40 * MI)
#define O_KL  (44 * MI)
#define O_VH  (48 * MI)
#define O_VL  (52 * MI)
#define O_VTH (56 * MI)
#define O_VTL (60 * MI)
#define O_CH  (64 * MI)
#define O_CL  (68 * MI)

__device__ __forceinline__ uint32_t smem_u32(const void* p) {
    uint32_t a;
    asm("{ .reg .u64 t; cvta.to.shared.u64 t, %1; cvt.u32.u64 %0, t; }" : "=r"(a) : "l"(p));
    return a;
}

#define LDSM4(r0, r1, r2, r3, addr) \
    asm volatile("ldmatrix.sync.aligned.m8n8.x4.shared.b16 {%0,%1,%2,%3}, [%4];" \
        : "=r"(r0), "=r"(r1), "=r"(r2), "=r"(r3) : "r"(addr))

#define MMA16816(d, a, b) \
    asm volatile("mma.sync.aligned.m16n8k16.row.col.f32.bf16.bf16.f32 " \
        "{%0,%1,%2,%3}, {%4,%5,%6,%7}, {%8,%9}, {%0,%1,%2,%3};" \
        : "+f"((d)[0]), "+f"((d)[1]), "+f"((d)[2]), "+f"((d)[3]) \
        : "r"((a)[0]), "r"((a)[1]), "r"((a)[2]), "r"((a)[3]), "r"((b)[0]), "r"((b)[1]))

#define CP16(dst, src) \
    asm volatile("cp.async.cg.shared.global [%0], [%1], 16;" :: "r"(dst), "l"(src))
#define CP_COMMIT() asm volatile("cp.async.commit_group;")
#define CP_WAIT(n)  asm volatile("cp.async.wait_group %0;" :: "n"(n))

// split (c0, c1) fp32 -> packed bf16x2 hi and lo (lo = residual)
__device__ __forceinline__ void split2(float c0, float c1, uint32_t& hi, uint32_t& lo) {
    asm("cvt.rn.bf16x2.f32 %0, %1, %2;" : "=r"(hi) : "f"(c1), "f"(c0));
    float f0 = __uint_as_float(hi << 16);
    float f1 = __uint_as_float(hi & 0xffff0000u);
    asm("cvt.rn.bf16x2.f32 %0, %1, %2;" : "=r"(lo) : "f"(c1 - f1), "f"(c0 - f0));
}

// Convert float4 -> bf16 hi/lo, store into SW128-swizzled K-major tile (row = 64 bf16 = 128B)
__device__ __forceinline__ void cvt_store(char* smem, int offHi, int offLo, int row, int c4, float4 v) {
    uint32_t hi01, hi23, lo01, lo23;
    split2(v.x, v.y, hi01, lo01);
    split2(v.z, v.w, hi23, lo23);
    uint32_t off = row * 128 + (c4 << 1);
    uint32_t sw = off ^ ((off >> 3) & 0x70);
    *(uint32_t*)(smem + offHi + sw)     = hi01;
    *(uint32_t*)(smem + offHi + sw + 4) = hi23;
    *(uint32_t*)(smem + offLo + sw)     = lo01;
    *(uint32_t*)(smem + offLo + sw + 4) = lo23;
}

// fp32 array -> hi/lo bf16 arrays in g_buf (4 elems per thread)
__global__ __launch_bounds__(256) void split_f32(const float* __restrict__ src,
                                                 long oh, long ol, long n4) {
    long i = (long)blockIdx.x * 256 + threadIdx.x;
    if (i >= n4) return;
    float4 v = ((const float4*)src)[i];
    uint32_t h01, h23, l01, l23;
    split2(v.x, v.y, h01, l01);
    split2(v.z, v.w, h23, l23);
    uint2 h; h.x = h01; h.y = h23;
    uint2 l; l.x = l01; l.y = l23;
    ((uint2*)(g_buf + oh))[i] = h;
    ((uint2*)(g_buf + ol))[i] = l;
}

// v [b, s, d] hi/lo -> vt [b, d, s] hi/lo
__global__ __launch_bounds__(256) void transpose_hl() {
    __shared__ unsigned short t[32][34];
    int b = blockIdx.z;
    int d0 = blockIdx.x * 32, s0 = blockIdx.y * 32;
    int tx = threadIdx.x, ty = threadIdx.y;
#pragma unroll
    for (int a = 0; a < 2; a++) {
        const unsigned short* src = (const unsigned short*)(g_buf + (a ? O_VL : O_VH)) + (long)b * SQ * DM;
        unsigned short* dst = (unsigned short*)(g_buf + (a ? O_VTL : O_VTH)) + (long)b * DM * SQ;
#pragma unroll
        for (int i = 0; i < 32; i += 8)
            t[ty + i][tx] = src[(long)(s0 + ty + i) * DM + d0 + tx];
        __syncthreads();
#pragma unroll
        for (int i = 0; i < 32; i += 8)
            dst[(long)(d0 + ty + i) * SQ + s0 + tx] = t[tx][ty + i];
        __syncthreads();
    }
}

// ---------------- HMMA GEMM, bf16x3, cp.async double-buffered ----------------
// C[m,n] = alpha*sum_k A[m,k]*B[n,k] (+bias). A,B hi/lo bf16 in g_buf (K-contig).
// MODE 0: normal. MODE 1: A = fp32 logits (Alog) with fused softmax; P written back.
// Output: Cf (fp32) if non-null, else hi/lo bf16 at oCh/oCl.
template<int NTILE, int MODE, int MINB>
__global__ void __launch_bounds__(256, MINB) mm_bf(
    long oAh, long oAl, int lda, long sAb, long sAh_,
    long oBh, long oBl, int ldb, long sBb, long sBh_,
    float* __restrict__ Cf, long oCh, long oCl, int ldc, long sCb, long sCh_,
    float* __restrict__ Alog, long sAlz,
    int K, float alpha, const float* __restrict__ bias, int H)
{
    extern __shared__ char smem[];
    constexpr int ABYT = 128 * 64 * 2;
    constexpr int BBYT = NTILE * 64 * 2;
    constexpr int WN = NTILE / 2;
    constexpr int NG = WN / 8;
    constexpr int BIT = NTILE * 8 / 256;
    constexpr int STAGE0 = 2 * ABYT + 2 * BBYT;   // MODE 0 stage stride
    constexpr int STAGEB = 2 * BBYT;              // MODE 1 B stage stride

    uint32_t sb = smem_u32(smem);
    int tid = threadIdx.x, wid = tid >> 5, lane = tid & 31;
    int warp_m = wid & 3, warp_n = wid >> 2;
    int z = blockIdx.z, b = z / H, h = z - b * H;
    long m0 = (long)blockIdx.y * 128, n0 = (long)blockIdx.x * NTILE;

    const __nv_bfloat16* pAh = g_buf + oAh + (long)b * sAb + (long)h * sAh_;
    const __nv_bfloat16* pAl = g_buf + oAl + (long)b * sAb + (long)h * sAh_;
    const __nv_bfloat16* pBh = g_buf + oBh + (long)b * sBb + (long)h * sBh_;
    const __nv_bfloat16* pBl = g_buf + oBl + (long)b * sBb + (long)h * sBh_;

    float* smM = (float*)smem;
    float* smI = (float*)(smem + 512);
    float* Lz = nullptr;

    if (MODE == 1) {
        Lz = Alog + (long)z * sAlz;
        // phase 1: per-row max & sum of exp (warp wid owns rows wid*16..wid*16+15)
        for (int rr = 0; rr < 16; rr++) {
            int row = wid * 16 + rr;
            const float4* R = (const float4*)(Lz + (m0 + row) * (long)SQ);
            float m = -3.4e38f;
#pragma unroll 4
            for (int i = 0; i < 16; i++) {
                float4 v = R[i * 32 + lane];
                m = fmaxf(m, fmaxf(fmaxf(v.x, v.y), fmaxf(v.z, v.w)));
            }
#pragma unroll
            for (int o = 16; o; o >>= 1) m = fmaxf(m, __shfl_xor_sync(~0u, m, o));
            float s = 0.f;
#pragma unroll 4
            for (int i = 0; i < 16; i++) {
                float4 v = R[i * 32 + lane];
                s += __expf(v.x - m) + __expf(v.y - m) + __expf(v.z - m) + __expf(v.w - m);
            }
#pragma unroll
            for (int o = 16; o; o >>= 1) s += __shfl_xor_sync(~0u, s, o);
            if (lane == 0) { smM[row] = m; smI[row] = 1.f / s; }
        }
        __syncthreads();
    }

    auto loadAB = [&](int stage, int c) {          // MODE 0: A + B hi/lo
        uint32_t aB = sb + 1024 + stage * STAGE0;
        uint32_t bB = aB + 2 * ABYT;
        int k0 = c << 6;
#pragma unroll
        for (int u = 0; u < 4; u++) {
            int unit = u * 256 + tid; int row = unit >> 3, seg = unit & 7;
            long gi = (m0 + row) * (long)lda + k0 + seg * 8;
            uint32_t d = aB + row * 128 + ((seg * 16) ^ ((row & 7) << 4));
            CP16(d, pAh + gi);
            CP16(d + ABYT, pAl + gi);
        }
#pragma unroll
        for (int u = 0; u < BIT; u++) {
            int unit = u * 256 + tid; int row = unit >> 3, seg = unit & 7;
            long gi = (n0 + row) * (long)ldb + k0 + seg * 8;
            uint32_t d = bB + row * 128 + ((seg * 16) ^ ((row & 7) << 4));
            CP16(d, pBh + gi);
            CP16(d + BBYT, pBl + gi);
        }
    };
    auto loadB1 = [&](int stage, int c) {          // MODE 1: B only
        uint32_t bB = sb + 1024 + 2 * ABYT + stage * STAGEB;
        int k0 = c << 6;
#pragma unroll
        for (int u = 0; u < BIT; u++) {
            int unit = u * 256 + tid; int row = unit >> 3, seg = unit & 7;
            long gi = (n0 + row) * (long)ldb + k0 + seg * 8;
            uint32_t d = bB + row * 128 + ((seg * 16) ^ ((row & 7) << 4));
            CP16(d, pBh + gi);
            CP16(d + BBYT, pBl + gi);
        }
    };

    float acc[2][NG][4] = {};
    const int nc = K >> 6;

    if (MODE == 0) { loadAB(0, 0); } else { loadB1(0, 0); }
    CP_COMMIT();

    for (int c = 0; c < nc; c++) {
        int st = c & 1;
        if (c + 1 < nc) {
            if (MODE == 0) loadAB((c + 1) & 1, c + 1); else loadB1((c + 1) & 1, c + 1);
            CP_COMMIT();
        }
        if (MODE == 1) {
            // fused softmax: read logits, write P to gmem, store bf16 hi/lo to smem A
            int k0 = c << 6;
#pragma unroll
            for (int u = 0; u < 8; u++) {
                int unit = u * 256 + tid; int row = unit >> 4, c4 = (unit & 15) << 2;
                long gi = (m0 + row) * (long)SQ + k0 + c4;
                float4 l = *(const float4*)(Lz + gi);
                float m = smM[row], is = smI[row];
                float4 p;
                p.x = __expf(l.x - m) * is; p.y = __expf(l.y - m) * is;
                p.z = __expf(l.z - m) * is; p.w = __expf(l.w - m) * is;
                *(float4*)(Lz + gi) = p;
                cvt_store(smem + 1024, 0, ABYT, row, c4, p);
            }
        }
        if (c + 1 < nc) CP_WAIT(1); else CP_WAIT(0);
        __syncthreads();

        uint32_t aB = MODE ? (sb + 1024) : (sb + 1024 + st * STAGE0);
        uint32_t bB = MODE ? (sb + 1024 + 2 * ABYT + st * STAGEB) : (aB + 2 * ABYT);
        int lrow = lane & 15, lcb = (lane >> 4) << 4;
#pragma unroll
        for (int ks = 0; ks < 4; ks++) {
            int cb = ks * 32 + lcb;
            uint32_t ah[2][4], al[2][4];
#pragma unroll
            for (int im = 0; im < 2; im++) {
                int row = warp_m * 32 + im * 16 + lrow;
                uint32_t ad = aB + row * 128 + (cb ^ ((row & 7) << 4));
                LDSM4(ah[im][0], ah[im][1], ah[im][2], ah[im][3], ad);
                LDSM4(al[im][0], al[im][1], al[im][2], al[im][3], ad + ABYT);
            }
            uint32_t bh_[NG][2], bl_[NG][2];
#pragma unroll
            for (int g2 = 0; g2 < NG / 2; g2++) {
                int row = warp_n * WN + g2 * 16 + lrow;
                uint32_t bd = bB + row * 128 + (cb ^ ((row & 7) << 4));
                uint32_t r0, r1, r2, r3;
                LDSM4(r0, r1, r2, r3, bd);
                bh_[2 * g2][0] = r0; bh_[2 * g2][1] = r2;
                bh_[2 * g2 + 1][0] = r1; bh_[2 * g2 + 1][1] = r3;
                LDSM4(r0, r1, r2, r3, bd + BBYT);
                bl_[2 * g2][0] = r0; bl_[2 * g2][1] = r2;
                bl_[2 * g2 + 1][0] = r1; bl_[2 * g2 + 1][1] = r3;
            }
#pragma unroll
            for (int im = 0; im < 2; im++)
#pragma unroll
                for (int g = 0; g < NG; g++)
                    MMA16816(acc[im][g], ah[im], bh_[g]);
#pragma unroll
            for (int im = 0; im < 2; im++)
#pragma unroll
                for (int g = 0; g < NG; g++) {
                    MMA16816(acc[im][g], ah[im], bl_[g]);
                    MMA16816(acc[im][g], al[im], bh_[g]);
                }
        }
        __syncthreads();
    }

    // epilogue
    if (Cf) {
        float* pC = Cf + (long)b * sCb + (long)h * sCh_;
#pragma unroll
        for (int im = 0; im < 2; im++) {
            long r0 = m0 + warp_m * 32 + im * 16 + (lane >> 2);
#pragma unroll
            for (int g = 0; g < NG; g++) {
                long col = n0 + warp_n * WN + g * 8 + (lane & 3) * 2;
                float bx = bias ? bias[col] : 0.f;
                float by = bias ? bias[col + 1] : 0.f;
                float2 o0, o1;
                o0.x = acc[im][g][0] * alpha + bx;
                o0.y = acc[im][g][1] * alpha + by;
                o1.x = acc[im][g][2] * alpha + bx;
                o1.y = acc[im][g][3] * alpha + by;
                *(float2*)(pC + r0 * (long)ldc + col) = o0;
                *(float2*)(pC + (r0 + 8) * (long)ldc + col) = o1;
            }
        }
    } else {
        __nv_bfloat16* pCh = g_buf + oCh + (long)b * sCb + (long)h * sCh_;
        __nv_bfloat16* pCl = g_buf + oCl + (long)b * sCb + (long)h * sCh_;
#pragma unroll
        for (int im = 0; im < 2; im++) {
            long r0 = m0 + warp_m * 32 + im * 16 + (lane >> 2);
#pragma unroll
            for (int g = 0; g < NG; g++) {
                long col = n0 + warp_n * WN + g * 8 + (lane & 3) * 2;
                float bx = bias ? bias[col] : 0.f;
                float by = bias ? bias[col + 1] : 0.f;
                float c0 = acc[im][g][0] * alpha + bx;
                float c1 = acc[im][g][1] * alpha + by;
                float c2 = acc[im][g][2] * alpha + bx;
                float c3 = acc[im][g][3] * alpha + by;
                uint32_t hA, lA, hB, lB;
                split2(c0, c1, hA, lA);
                split2(c2, c3, hB, lB);
                *(uint32_t*)(pCh + r0 * (long)ldc + col) = hA;
                *(uint32_t*)(pCl + r0 * (long)ldc + col) = lA;
                *(uint32_t*)(pCh + (r0 + 8) * (long)ldc + col) = hB;
                *(uint32_t*)(pCl + (r0 + 8) * (long)ldc + col) = lB;
            }
        }
    }
}

extern "C" void kernel_launch(void* const* d_in, const int* in_sizes, int n_in,
                              void* d_out, int out_size) {
    const float* query = (const float*)d_in[0];
    const float* key   = (const float*)d_in[1];
    const float* value = (const float*)d_in[2];
    const float* Wq = (const float*)d_in[3];
    const float* bq = (const float*)d_in[4];
    const float* Wk = (const float*)d_in[5];
    const float* bk = (const float*)d_in[6];
    const float* Wv = (const float*)d_in[7];
    const float* bv = (const float*)d_in[8];
    const float* Wo = (const float*)d_in[9];
    const float* bo = (const float*)d_in[10];

    float* out = (float*)d_out;
    float* scores = out + (long)NB * SQ * DM;   // [B, H, S, S]

    const long NIN = (long)NB * SQ * DM;   // 4M
    const long NW  = (long)DM * DM;        // 1M

    // split fp32 -> bf16 hi/lo
    split_f32<<<(unsigned)(NIN / 4 / 256), 256>>>(query, O_INH, O_INL, NIN / 4);
    split_f32<<<(unsigned)(NIN / 4 / 256), 256>>>(key,   O_INH + 4 * MI, O_INL + 4 * MI, NIN / 4);
    split_f32<<<(unsigned)(NIN / 4 / 256), 256>>>(value, O_INH + 8 * MI, O_INL + 8 * MI, NIN / 4);
    split_f32<<<(unsigned)(NW / 4 / 256), 256>>>(Wq, O_WH + 0 * MI, O_WL + 0 * MI, NW / 4);
    split_f32<<<(unsigned)(NW / 4 / 256), 256>>>(Wk, O_WH + 1 * MI, O_WL + 1 * MI, NW / 4);
    split_f32<<<(unsigned)(NW / 4 / 256), 256>>>(Wv, O_WH + 2 * MI, O_WL + 2 * MI, NW / 4);
    split_f32<<<(unsigned)(NW / 4 / 256), 256>>>(Wo, O_WH + 3 * MI, O_WL + 3 * MI, NW / 4);

    const int SM_M0 = 1024 + 2 * (2 * 128 * 64 * 2 + 2 * 128 * 64 * 2);   // 132096
    const int SM_M1 = 1024 + 2 * 128 * 64 * 2 + 2 * (2 * 64 * 64 * 2);    // 66560
    cudaFuncSetAttribute(mm_bf<128, 0, 1>, cudaFuncAttributeMaxDynamicSharedMemorySize, SM_M0);
    cudaFuncSetAttribute(mm_bf<64, 1, 2>,  cudaFuncAttributeMaxDynamicSharedMemorySize, SM_M1);

    dim3 gproj(8, 32, 1);
    // q/k/v projections -> hi/lo scratch
    mm_bf<128, 0, 1><<<gproj, 256, SM_M0>>>(
        O_INH, O_INL, DM, 0, 0, O_WH, O_WL, DM, 0, 0,
        nullptr, O_QH, O_QL, DM, 0, 0, nullptr, 0, DM, 1.f, bq, 1);
    mm_bf<128, 0, 1><<<gproj, 256, SM_M0>>>(
        O_INH + 4 * MI, O_INL + 4 * MI, DM, 0, 0, O_WH + 1 * MI, O_WL + 1 * MI, DM, 0, 0,
        nullptr, O_KH, O_KL, DM, 0, 0, nullptr, 0, DM, 1.f, bk, 1);
    mm_bf<128, 0, 1><<<gproj, 256, SM_M0>>>(
        O_INH + 8 * MI, O_INL + 8 * MI, DM, 0, 0, O_WH + 2 * MI, O_WL + 2 * MI, DM, 0, 0,
        nullptr, O_VH, O_VL, DM, 0, 0, nullptr, 0, DM, 1.f, bv, 1);

    // v -> vt
    transpose_hl<<<dim3(DM / 32, SQ / 32, NB), dim3(32, 8)>>>();

    // logits = (q @ k^T) / 8 -> scores (fp32)
    dim3 gqk(16, 16, NB * NH);
    mm_bf<128, 0, 1><<<gqk, 256, SM_M0>>>(
        O_QH, O_QL, DM, (long)SQ * DM, DK, O_KH, O_KL, DM, (long)SQ * DM, DK,
        scores, 0, 0, SQ, (long)NH * SQ * SQ, (long)SQ * SQ, nullptr, 0, DK, 0.125f, nullptr, NH);

    // fused softmax + PV: P written into scores, ctx -> hi/lo
    dim3 gpv(1, 16, NB * NH);
    mm_bf<64, 1, 2><<<gpv, 256, SM_M1>>>(
        0, 0, SQ, 0, 0, O_VTH, O_VTL, SQ, (long)DM * SQ, (long)DK * SQ,
        nullptr, O_CH, O_CL, DM, (long)SQ * DM, DK,
        scores, (long)SQ * SQ, SQ, 1.f, nullptr, NH);

    // out = ctx @ Wo^T + bo
    mm_bf<128, 0, 1><<<gproj, 256, SM_M0>>>(
        O_CH, O_CL, DM, 0, 0, O_WH + 3 * MI, O_WL + 3 * MI, DM, 0, 0,
        out, 0, 0, DM, 0, 0, nullptr, 0, DM, 1.f, bo, 1);
}